// round 1
// baseline (speedup 1.0000x reference)
#include <cuda_runtime.h>
#include <math.h>

#define TT   4096
#define HID  2048
#define NH   32
#define HD   128
#define PP   4096   // NH * HD
#define TP   (TT * PP)

// ---------------- scratch (device globals; no allocations allowed) ----------
__device__ float g_qp[TP];
__device__ float g_kp[TP];
__device__ float g_vp[TP];
__device__ float g_q [TP];
__device__ float g_k [TP];
__device__ float g_v [TP];
__device__ float g_eg[TP];   // holds raw fa@Wfb, then exp(g1) in place
__device__ float g_g2[TP];
__device__ float g_o [TP];
__device__ float g_fa[TT * HD];
__device__ float g_ga[TT * HD];
__device__ float g_beta[TT * NH];

// ---------------- fp32 SGEMM: C[M,N] = A[M,K] @ B[K,N], row-major ----------
// BM=BN=128, BK=8, 256 threads, 8x8 per-thread microtile.
// Requirements used here: M % 128 == 0, K % 8 == 0, N % 4 == 0 (N guarded).
__global__ __launch_bounds__(256) void sgemm_k(const float* __restrict__ A,
                                               const float* __restrict__ B,
                                               float* __restrict__ C,
                                               int M, int N, int K) {
    __shared__ float As[8][128];
    __shared__ float Bs[8][128];
    const int bm = blockIdx.y * 128;
    const int bn = blockIdx.x * 128;
    const int tid = threadIdx.x;
    const int tr = tid >> 4, tc = tid & 15;
    const int row0 = tr * 8, col0 = tc * 8;
    const int arow = tid >> 1, acol = (tid & 1) * 4;
    const int brow = tid >> 5, bcol = (tid & 31) * 4;

    float acc[8][8];
#pragma unroll
    for (int i = 0; i < 8; i++)
#pragma unroll
        for (int j = 0; j < 8; j++) acc[i][j] = 0.f;

    const float* Aptr = A + (size_t)(bm + arow) * K + acol;
    const int gc = bn + bcol;

    for (int k0 = 0; k0 < K; k0 += 8) {
        float4 av = *reinterpret_cast<const float4*>(Aptr + k0);
        As[acol + 0][arow] = av.x;
        As[acol + 1][arow] = av.y;
        As[acol + 2][arow] = av.z;
        As[acol + 3][arow] = av.w;
        float4 bv = make_float4(0.f, 0.f, 0.f, 0.f);
        if (gc < N)
            bv = *reinterpret_cast<const float4*>(B + (size_t)(k0 + brow) * N + gc);
        *reinterpret_cast<float4*>(&Bs[brow][bcol]) = bv;
        __syncthreads();
#pragma unroll
        for (int kk = 0; kk < 8; kk++) {
            float4 a0 = *reinterpret_cast<const float4*>(&As[kk][row0]);
            float4 a1 = *reinterpret_cast<const float4*>(&As[kk][row0 + 4]);
            float4 b0 = *reinterpret_cast<const float4*>(&Bs[kk][col0]);
            float4 b1 = *reinterpret_cast<const float4*>(&Bs[kk][col0 + 4]);
            float avv[8] = {a0.x, a0.y, a0.z, a0.w, a1.x, a1.y, a1.z, a1.w};
            float bvv[8] = {b0.x, b0.y, b0.z, b0.w, b1.x, b1.y, b1.z, b1.w};
#pragma unroll
            for (int i = 0; i < 8; i++)
#pragma unroll
                for (int j = 0; j < 8; j++) acc[i][j] += avv[i] * bvv[j];
        }
        __syncthreads();
    }

#pragma unroll
    for (int i = 0; i < 8; i++) {
        const int r = bm + row0 + i;
#pragma unroll
        for (int j = 0; j < 8; j += 4) {
            const int c = bn + col0 + j;
            if (c < N) {
                float4 o4 = make_float4(acc[i][j], acc[i][j + 1], acc[i][j + 2], acc[i][j + 3]);
                *reinterpret_cast<float4*>(C + (size_t)r * N + c) = o4;
            }
        }
    }
}

// ---------------- depthwise causal conv (K=4) + SiLU (+ optional scale) ----
__global__ __launch_bounds__(256) void conv_silu_k(const float* __restrict__ x,
                                                   const float* __restrict__ w,
                                                   float* __restrict__ y, float scale) {
    const int idx = blockIdx.x * 256 + threadIdx.x;  // over T*P
    const int t = idx >> 12;
    const int p = idx & (PP - 1);
    const float4 wv = *reinterpret_cast<const float4*>(w + p * 4);
    float acc = x[idx] * wv.w;
    if (t >= 1) acc += x[idx - PP] * wv.z;
    if (t >= 2) acc += x[idx - 2 * PP] * wv.y;
    if (t >= 3) acc += x[idx - 3 * PP] * wv.x;
    const float sg = 1.f / (1.f + expf(-acc));
    y[idx] = acc * sg * scale;
}

// ---------------- beta = 2*sigmoid(raw), in place ---------------------------
__global__ void beta_k(float* __restrict__ b) {
    const int idx = blockIdx.x * 256 + threadIdx.x;
    if (idx < TT * NH) {
        const float x = b[idx];
        b[idx] = 2.f / (1.f + expf(-x));
    }
}

// ---------------- eg = exp(-5 * sigmoid(exp(A_log[h]) * (raw + dt_bias))) --
__global__ __launch_bounds__(256) void gate_k(float* __restrict__ g,
                                              const float* __restrict__ dt_bias,
                                              const float* __restrict__ A_log) {
    const int idx = blockIdx.x * 256 + threadIdx.x;  // over T*P
    const int p = idx & (PP - 1);
    const int h = p >> 7;
    const float a = expf(A_log[h]);
    const float x = g[idx] + dt_bias[p];
    const float sg = 1.f / (1.f + expf(-a * x));
    g[idx] = expf(-5.f * sg);
}

// ---------------- KDA scan ---------------------------------------------------
// Column-independent in dv: CTA = (head, 32-col block), 8 threads per column,
// 16 state elements per thread. Double-buffered register prefetch over t.
struct Step {
    float k[16], q[16], e[16];
    float v, b;
};

__device__ __forceinline__ void ld16(float* d, const float* s) {
    float4 v0 = *reinterpret_cast<const float4*>(s);
    float4 v1 = *reinterpret_cast<const float4*>(s + 4);
    float4 v2 = *reinterpret_cast<const float4*>(s + 8);
    float4 v3 = *reinterpret_cast<const float4*>(s + 12);
    d[0] = v0.x; d[1] = v0.y; d[2]  = v0.z; d[3]  = v0.w;
    d[4] = v1.x; d[5] = v1.y; d[6]  = v1.z; d[7]  = v1.w;
    d[8] = v2.x; d[9] = v2.y; d[10] = v2.z; d[11] = v2.w;
    d[12] = v3.x; d[13] = v3.y; d[14] = v3.z; d[15] = v3.w;
}

__device__ __forceinline__ void fetch_step(Step& st, int t, int off_kqe, int off_v, int h,
                                           const float* __restrict__ q,
                                           const float* __restrict__ k,
                                           const float* __restrict__ v,
                                           const float* __restrict__ eg,
                                           const float* __restrict__ beta) {
    const int base = t * PP;
    ld16(st.k, k + base + off_kqe);
    ld16(st.q, q + base + off_kqe);
    ld16(st.e, eg + base + off_kqe);
    st.v = v[base + off_v];
    st.b = beta[t * NH + h];
}

__device__ __forceinline__ void do_step(float* S, const Step& st,
                                        float* __restrict__ o, int t, int off_v, int s) {
    float p0 = 0.f, p1 = 0.f;
#pragma unroll
    for (int r = 0; r < 16; r += 2) {
        S[r]     *= st.e[r];     p0 += S[r]     * st.k[r];
        S[r + 1] *= st.e[r + 1]; p1 += S[r + 1] * st.k[r + 1];
    }
    float part = p0 + p1;
    part += __shfl_xor_sync(0xffffffffu, part, 1);
    part += __shfl_xor_sync(0xffffffffu, part, 2);
    part += __shfl_xor_sync(0xffffffffu, part, 4);
    const float u = st.b * (st.v - part);
    float o0 = 0.f, o1 = 0.f;
#pragma unroll
    for (int r = 0; r < 16; r += 2) {
        S[r]     += st.k[r] * u;     o0 += st.q[r]     * S[r];
        S[r + 1] += st.k[r + 1] * u; o1 += st.q[r + 1] * S[r + 1];
    }
    float po = o0 + o1;
    po += __shfl_xor_sync(0xffffffffu, po, 1);
    po += __shfl_xor_sync(0xffffffffu, po, 2);
    po += __shfl_xor_sync(0xffffffffu, po, 4);
    if (s == 0) o[t * PP + off_v] = po;
}

__global__ __launch_bounds__(256) void scan_k(const float* __restrict__ q,
                                              const float* __restrict__ k,
                                              const float* __restrict__ v,
                                              const float* __restrict__ eg,
                                              const float* __restrict__ beta,
                                              float* __restrict__ o) {
    const int h = blockIdx.y;
    const int jl = threadIdx.x >> 3;
    const int s = threadIdx.x & 7;
    const int j = blockIdx.x * 32 + jl;
    const int off_kqe = h * HD + s * 16;
    const int off_v = h * HD + j;

    float S[16];
#pragma unroll
    for (int r = 0; r < 16; r++) S[r] = 0.f;

    Step A, B;
    fetch_step(A, 0, off_kqe, off_v, h, q, k, v, eg, beta);
    for (int t = 0; t < TT; t += 2) {
        fetch_step(B, t + 1, off_kqe, off_v, h, q, k, v, eg, beta);
        do_step(S, A, o, t, off_v, s);
        const int t2 = (t + 2 < TT) ? (t + 2) : (TT - 1);
        fetch_step(A, t2, off_kqe, off_v, h, q, k, v, eg, beta);
        do_step(S, B, o, t + 1, off_v, s);
    }
}

// ---------------- gated RMSNorm: o = o * rsqrt(mean(o^2)+eps) * w * sig(g2) -
__global__ __launch_bounds__(256) void rmsnorm_k(float* __restrict__ o,
                                                 const float* __restrict__ g2,
                                                 const float* __restrict__ w) {
    const int warp = (blockIdx.x * blockDim.x + threadIdx.x) >> 5;  // (t*NH + h)
    const int lane = threadIdx.x & 31;
    if (warp >= TT * NH) return;
    const int base = warp * HD + lane * 4;
    float4 x = *reinterpret_cast<const float4*>(o + base);
    float ss = x.x * x.x + x.y * x.y + x.z * x.z + x.w * x.w;
#pragma unroll
    for (int d = 16; d > 0; d >>= 1) ss += __shfl_xor_sync(0xffffffffu, ss, d);
    const float rstd = rsqrtf(ss * (1.f / 128.f) + 1e-5f);
    const float4 g = *reinterpret_cast<const float4*>(g2 + base);
    const float4 wv = *reinterpret_cast<const float4*>(w + lane * 4);
    float4 r;
    r.x = x.x * rstd * wv.x / (1.f + expf(-g.x));
    r.y = x.y * rstd * wv.y / (1.f + expf(-g.y));
    r.z = x.z * rstd * wv.z / (1.f + expf(-g.z));
    r.w = x.w * rstd * wv.w / (1.f + expf(-g.w));
    *reinterpret_cast<float4*>(o + base) = r;
}

// ---------------- launch -----------------------------------------------------
extern "C" void kernel_launch(void* const* d_in, const int* in_sizes, int n_in,
                              void* d_out, int out_size) {
    const float* hs   = (const float*)d_in[0];
    const float* Wq   = (const float*)d_in[1];
    const float* Wk   = (const float*)d_in[2];
    const float* Wv   = (const float*)d_in[3];
    const float* cq   = (const float*)d_in[4];
    const float* ck   = (const float*)d_in[5];
    const float* cv   = (const float*)d_in[6];
    const float* Wb   = (const float*)d_in[7];
    const float* Wfa  = (const float*)d_in[8];
    const float* Wfb  = (const float*)d_in[9];
    const float* dtb  = (const float*)d_in[10];
    const float* Alog = (const float*)d_in[11];
    const float* Wga  = (const float*)d_in[12];
    const float* Wgb  = (const float*)d_in[13];
    const float* onw  = (const float*)d_in[14];
    const float* Wo   = (const float*)d_in[15];
    float* out = (float*)d_out;

    float *qp, *kp, *vp, *q, *k, *v, *eg, *g2, *o, *fa, *ga, *beta;
    cudaGetSymbolAddress((void**)&qp, g_qp);
    cudaGetSymbolAddress((void**)&kp, g_kp);
    cudaGetSymbolAddress((void**)&vp, g_vp);
    cudaGetSymbolAddress((void**)&q,  g_q);
    cudaGetSymbolAddress((void**)&k,  g_k);
    cudaGetSymbolAddress((void**)&v,  g_v);
    cudaGetSymbolAddress((void**)&eg, g_eg);
    cudaGetSymbolAddress((void**)&g2, g_g2);
    cudaGetSymbolAddress((void**)&o,  g_o);
    cudaGetSymbolAddress((void**)&fa, g_fa);
    cudaGetSymbolAddress((void**)&ga, g_ga);
    cudaGetSymbolAddress((void**)&beta, g_beta);

    const dim3 blk(256);
    const dim3 gBig(PP / 128, TT / 128);         // N=4096
    const dim3 gSmallN(1, TT / 128);             // N=128 or N=32
    const dim3 gOut(HID / 128, TT / 128);        // N=2048

    // projections
    sgemm_k<<<gBig, blk>>>(hs, Wq, qp, TT, PP, HID);
    sgemm_k<<<gBig, blk>>>(hs, Wk, kp, TT, PP, HID);
    sgemm_k<<<gBig, blk>>>(hs, Wv, vp, TT, PP, HID);
    sgemm_k<<<gSmallN, blk>>>(hs, Wfa, fa, TT, HD, HID);
    sgemm_k<<<gSmallN, blk>>>(hs, Wga, ga, TT, HD, HID);
    sgemm_k<<<gSmallN, blk>>>(hs, Wb, beta, TT, NH, HID);

    // conv + silu (+ q scale 1/sqrt(128))
    conv_silu_k<<<TP / 256, blk>>>(qp, cq, q, 0.08838834764831845f);
    conv_silu_k<<<TP / 256, blk>>>(kp, ck, k, 1.f);
    conv_silu_k<<<TP / 256, blk>>>(vp, cv, v, 1.f);

    // gates
    beta_k<<<(TT * NH + 255) / 256, blk>>>(beta);
    sgemm_k<<<gBig, blk>>>(fa, Wfb, eg, TT, PP, HD);
    gate_k<<<TP / 256, blk>>>(eg, dtb, Alog);
    sgemm_k<<<gBig, blk>>>(ga, Wgb, g2, TT, PP, HD);

    // sequential KDA scan (128 CTAs: 32 heads x 4 column-blocks)
    scan_k<<<dim3(4, NH), blk>>>(q, k, v, eg, beta, o);

    // gated rmsnorm + output projection
    rmsnorm_k<<<(TT * NH * 32) / 256, blk>>>(o, g2, onw);
    sgemm_k<<<gOut, blk>>>(o, Wo, out, TT, HID, PP);
}

// round 3
// speedup vs baseline: 1.5559x; 1.5559x over previous
#include <cuda_runtime.h>
#include <math.h>
#include <stdint.h>

#define TT   4096
#define HID  2048
#define NH   32
#define HD   128
#define PP   4096
#define TP   (TT * PP)

// ---------------- scratch (device globals; no allocations allowed) ----------
__device__ float g_qp[TP];
__device__ float g_kp[TP];
__device__ float g_vp[TP];
__device__ float g_q [TP];
__device__ float g_k [TP];
__device__ float g_v [TP];
__device__ float g_eg[TP];
__device__ float g_g2[TP];
__device__ float g_o [TP];
__device__ float g_fa[TT * HD];
__device__ float g_ga[TT * HD];
__device__ float g_beta[TT * NH];
// rounded (+padded) weights
__device__ float g_wqR[HID * PP];
__device__ float g_wkR[HID * PP];
__device__ float g_wvR[HID * PP];
__device__ float g_woR[PP * HID];
__device__ float g_wfbR[HD * PP];
__device__ float g_wgbR[HD * PP];
__device__ float g_wfaR[HID * HD];
__device__ float g_wgaR[HID * HD];
__device__ float g_wbR [HID * HD];   // Wb padded 32 -> 128 cols

// ---------------- helpers -----------------------------------------------------
__device__ __forceinline__ uint32_t smem_u32(const void* p) {
    uint32_t a;
    asm("{ .reg .u64 t; cvta.to.shared.u64 t, %1; cvt.u32.u64 %0, t; }" : "=r"(a) : "l"(p));
    return a;
}
__device__ __forceinline__ float rna_tf32(float x) {
    uint32_t o, i = __float_as_uint(x);
    asm("cvt.rna.tf32.f32 %0, %1;" : "=r"(o) : "r"(i));
    return __uint_as_float(o);
}
__device__ __forceinline__ void cp_async16(uint32_t dst, const float* src) {
    asm volatile("cp.async.cg.shared.global [%0], [%1], 16;\n"
                 :: "r"(dst), "l"(__cvta_generic_to_global(src)));
}
__device__ __forceinline__ void cp_commit() { asm volatile("cp.async.commit_group;\n" ::: "memory"); }

#define MMA_TF32(d, a, b)                                                      \
    asm volatile("mma.sync.aligned.m16n8k8.row.col.f32.tf32.tf32.f32 "        \
                 "{%0,%1,%2,%3}, {%4,%5,%6,%7}, {%8,%9}, {%0,%1,%2,%3};"      \
                 : "+f"((d)[0]), "+f"((d)[1]), "+f"((d)[2]), "+f"((d)[3])     \
                 : "r"((a)[0]), "r"((a)[1]), "r"((a)[2]), "r"((a)[3]),        \
                   "r"((b)[0]), "r"((b)[1]))

// ---------------- tf32 mma.sync GEMM ------------------------------------------
// C[M, Nvalid] = A[M,K] @ B[K,Npad] (B pre-rounded tf32; Npad multiple of 128).
// CTA tile 128x128x32, 8 warps (warp tile 64x32), double-buffered SMEM.
#define BM 128
#define BN 128
#define BK 32
#define SST 136   // smem row stride in floats: 136 % 32 == 8 -> conflict-free
#define GEMM_SMEM (2 * 2 * BK * SST * 4)

__global__ __launch_bounds__(256) void mma_gemm(const float* __restrict__ A,
                                                const float* __restrict__ B,
                                                float* __restrict__ C,
                                                int Nvalid, int Npad, int K) {
    extern __shared__ float sm[];
    float* As = sm;                       // [2][BK][SST]
    float* Bs = sm + 2 * BK * SST;        // [2][BK][SST]
    const uint32_t bs_u32 = smem_u32(Bs);

    const int tid = threadIdx.x;
    const int wid = tid >> 5, lane = tid & 31;
    const int g = lane >> 2, tig = lane & 3;
    const int wm = (wid & 1) * 64, wn = (wid >> 1) * 32;
    const int bm = blockIdx.y * BM, bn = blockIdx.x * BN;
    const int mA = tid & 31, kqA = tid >> 5;   // A staging: row mA(+32j), k quad kqA
    const int kB = tid >> 3, nqB = tid & 7;    // B staging: row kB, col quad nqB(+8j)
    const int NC = K >> 5;

    float acc[4][4][4];
#pragma unroll
    for (int i = 0; i < 4; i++)
#pragma unroll
        for (int j = 0; j < 4; j++)
#pragma unroll
            for (int r = 0; r < 4; r++) acc[i][j][r] = 0.f;

    float4 areg[4];

#define LDGA(chunk) do {                                                        \
        const int kb = (chunk) * BK;                                            \
        _Pragma("unroll")                                                       \
        for (int j = 0; j < 4; j++)                                             \
            areg[j] = *reinterpret_cast<const float4*>(                         \
                A + (size_t)(bm + mA + 32 * j) * K + kb + kqA * 4);             \
    } while (0)

#define STSA(buf) do {                                                          \
        float* d = As + (buf) * BK * SST;                                       \
        _Pragma("unroll")                                                       \
        for (int j = 0; j < 4; j++) {                                           \
            const int m = mA + 32 * j;                                          \
            d[(kqA * 4 + 0) * SST + m] = rna_tf32(areg[j].x);                   \
            d[(kqA * 4 + 1) * SST + m] = rna_tf32(areg[j].y);                   \
            d[(kqA * 4 + 2) * SST + m] = rna_tf32(areg[j].z);                   \
            d[(kqA * 4 + 3) * SST + m] = rna_tf32(areg[j].w);                   \
        }                                                                       \
    } while (0)

#define LDB(chunk, buf) do {                                                    \
        const int kb = (chunk) * BK;                                            \
        const uint32_t drow = bs_u32 + ((buf) * BK + kB) * SST * 4;             \
        const float* srow = B + (size_t)(kb + kB) * Npad + bn;                  \
        _Pragma("unroll")                                                       \
        for (int j = 0; j < 4; j++)                                             \
            cp_async16(drow + (nqB + 8 * j) * 16, srow + (nqB + 8 * j) * 4);    \
        cp_commit();                                                            \
    } while (0)

    // prologue
    LDGA(0);
    LDB(0, 0);
    STSA(0);

    for (int i = 0; i < NC; i++) {
        const int buf = i & 1;
        if (i + 1 < NC) {
            LDGA(i + 1);
            LDB(i + 1, buf ^ 1);
            asm volatile("cp.async.wait_group 1;\n" ::: "memory");
        } else {
            asm volatile("cp.async.wait_group 0;\n" ::: "memory");
        }
        __syncthreads();

        const float* ab = As + buf * BK * SST;
        const float* bb = Bs + buf * BK * SST;
#pragma unroll
        for (int s = 0; s < 4; s++) {
            uint32_t af[4][4], bf[4][2];
            const float* r0 = ab + (8 * s + tig) * SST + wm;
            const float* r1 = ab + (8 * s + tig + 4) * SST + wm;
#pragma unroll
            for (int mf = 0; mf < 4; mf++) {
                af[mf][0] = __float_as_uint(r0[16 * mf + g]);
                af[mf][1] = __float_as_uint(r0[16 * mf + g + 8]);
                af[mf][2] = __float_as_uint(r1[16 * mf + g]);
                af[mf][3] = __float_as_uint(r1[16 * mf + g + 8]);
            }
            const float* b0 = bb + (8 * s + tig) * SST + wn;
            const float* b1 = bb + (8 * s + tig + 4) * SST + wn;
#pragma unroll
            for (int nf = 0; nf < 4; nf++) {
                bf[nf][0] = __float_as_uint(b0[8 * nf + g]);
                bf[nf][1] = __float_as_uint(b1[8 * nf + g]);
            }
#pragma unroll
            for (int mf = 0; mf < 4; mf++)
#pragma unroll
                for (int nf = 0; nf < 4; nf++)
                    MMA_TF32(acc[mf][nf], af[mf], bf[nf]);
        }

        if (i + 1 < NC) STSA(buf ^ 1);
        __syncthreads();
    }

    // epilogue
#pragma unroll
    for (int mf = 0; mf < 4; mf++) {
        const int row0 = bm + wm + 16 * mf + g;
#pragma unroll
        for (int nf = 0; nf < 4; nf++) {
            const int col = bn + wn + 8 * nf + 2 * tig;
            if (col < Nvalid) {
                float2 lo = make_float2(acc[mf][nf][0], acc[mf][nf][1]);
                float2 hi = make_float2(acc[mf][nf][2], acc[mf][nf][3]);
                *reinterpret_cast<float2*>(C + (size_t)row0 * Nvalid + col) = lo;
                *reinterpret_cast<float2*>(C + (size_t)(row0 + 8) * Nvalid + col) = hi;
            }
        }
    }
}

// ---------------- weight prep: rounded tf32 copy (+ right-pad with zeros) ---
__global__ void prep_w(const float* __restrict__ in, float* __restrict__ out,
                       int N, int Npad, int total) {
    const int idx = blockIdx.x * 256 + threadIdx.x;
    if (idx >= total) return;
    const int k = idx / Npad, n = idx % Npad;
    out[idx] = (n < N) ? rna_tf32(in[(size_t)k * N + n]) : 0.f;
}

// ---------------- depthwise causal conv (K=4) + SiLU (+ scale) --------------
__global__ __launch_bounds__(256) void conv_silu_k(const float* __restrict__ x,
                                                   const float* __restrict__ w,
                                                   float* __restrict__ y, float scale) {
    const int idx = blockIdx.x * 256 + threadIdx.x;
    const int t = idx >> 12;
    const int p = idx & (PP - 1);
    const float4 wv = *reinterpret_cast<const float4*>(w + p * 4);
    float acc = x[idx] * wv.w;
    if (t >= 1) acc += x[idx - PP] * wv.z;
    if (t >= 2) acc += x[idx - 2 * PP] * wv.y;
    if (t >= 3) acc += x[idx - 3 * PP] * wv.x;
    const float sg = 1.f / (1.f + expf(-acc));
    y[idx] = acc * sg * scale;
}

__global__ void beta_k(float* __restrict__ b) {
    const int idx = blockIdx.x * 256 + threadIdx.x;
    if (idx < TT * NH) b[idx] = 2.f / (1.f + expf(-b[idx]));
}

__global__ __launch_bounds__(256) void gate_k(float* __restrict__ g,
                                              const float* __restrict__ dt_bias,
                                              const float* __restrict__ A_log) {
    const int idx = blockIdx.x * 256 + threadIdx.x;
    const int p = idx & (PP - 1);
    const int h = p >> 7;
    const float a = expf(A_log[h]);
    const float x = g[idx] + dt_bias[p];
    const float sg = 1.f / (1.f + expf(-a * x));
    g[idx] = expf(-5.f * sg);
}

// ---------------- KDA scan ----------------------------------------------------
struct Step { float k[16], q[16], e[16]; float v, b; };

__device__ __forceinline__ void ld16(float* d, const float* s) {
    float4 v0 = *reinterpret_cast<const float4*>(s);
    float4 v1 = *reinterpret_cast<const float4*>(s + 4);
    float4 v2 = *reinterpret_cast<const float4*>(s + 8);
    float4 v3 = *reinterpret_cast<const float4*>(s + 12);
    d[0] = v0.x; d[1] = v0.y; d[2]  = v0.z; d[3]  = v0.w;
    d[4] = v1.x; d[5] = v1.y; d[6]  = v1.z; d[7]  = v1.w;
    d[8] = v2.x; d[9] = v2.y; d[10] = v2.z; d[11] = v2.w;
    d[12] = v3.x; d[13] = v3.y; d[14] = v3.z; d[15] = v3.w;
}

__device__ __forceinline__ void fetch_step(Step& st, int t, int off_kqe, int off_v, int h,
                                           const float* __restrict__ q,
                                           const float* __restrict__ k,
                                           const float* __restrict__ v,
                                           const float* __restrict__ eg,
                                           const float* __restrict__ beta) {
    const int base = t * PP;
    ld16(st.k, k + base + off_kqe);
    ld16(st.q, q + base + off_kqe);
    ld16(st.e, eg + base + off_kqe);
    st.v = v[base + off_v];
    st.b = beta[t * NH + h];
}

__device__ __forceinline__ void do_step(float* S, const Step& st,
                                        float* __restrict__ o, int t, int off_v, int s) {
    float p0 = 0.f, p1 = 0.f;
#pragma unroll
    for (int r = 0; r < 16; r += 2) {
        S[r]     *= st.e[r];     p0 += S[r]     * st.k[r];
        S[r + 1] *= st.e[r + 1]; p1 += S[r + 1] * st.k[r + 1];
    }
    float part = p0 + p1;
    part += __shfl_xor_sync(0xffffffffu, part, 1);
    part += __shfl_xor_sync(0xffffffffu, part, 2);
    part += __shfl_xor_sync(0xffffffffu, part, 4);
    const float u = st.b * (st.v - part);
    float o0 = 0.f, o1 = 0.f;
#pragma unroll
    for (int r = 0; r < 16; r += 2) {
        S[r]     += st.k[r] * u;     o0 += st.q[r]     * S[r];
        S[r + 1] += st.k[r + 1] * u; o1 += st.q[r + 1] * S[r + 1];
    }
    float po = o0 + o1;
    po += __shfl_xor_sync(0xffffffffu, po, 1);
    po += __shfl_xor_sync(0xffffffffu, po, 2);
    po += __shfl_xor_sync(0xffffffffu, po, 4);
    if (s == 0) o[t * PP + off_v] = po;
}

__global__ __launch_bounds__(256) void scan_k(const float* __restrict__ q,
                                              const float* __restrict__ k,
                                              const float* __restrict__ v,
                                              const float* __restrict__ eg,
                                              const float* __restrict__ beta,
                                              float* __restrict__ o) {
    const int h = blockIdx.y;
    const int jl = threadIdx.x >> 3;
    const int s = threadIdx.x & 7;
    const int j = blockIdx.x * 32 + jl;
    const int off_kqe = h * HD + s * 16;
    const int off_v = h * HD + j;

    float S[16];
#pragma unroll
    for (int r = 0; r < 16; r++) S[r] = 0.f;

    Step A, B;
    fetch_step(A, 0, off_kqe, off_v, h, q, k, v, eg, beta);
    for (int t = 0; t < TT; t += 2) {
        fetch_step(B, t + 1, off_kqe, off_v, h, q, k, v, eg, beta);
        do_step(S, A, o, t, off_v, s);
        const int t2 = (t + 2 < TT) ? (t + 2) : (TT - 1);
        fetch_step(A, t2, off_kqe, off_v, h, q, k, v, eg, beta);
        do_step(S, B, o, t + 1, off_v, s);
    }
}

// ---------------- gated RMSNorm ------------------------------------------------
__global__ __launch_bounds__(256) void rmsnorm_k(float* __restrict__ o,
                                                 const float* __restrict__ g2,
                                                 const float* __restrict__ w) {
    const int warp = (blockIdx.x * blockDim.x + threadIdx.x) >> 5;
    const int lane = threadIdx.x & 31;
    if (warp >= TT * NH) return;
    const int base = warp * HD + lane * 4;
    float4 x = *reinterpret_cast<const float4*>(o + base);
    float ss = x.x * x.x + x.y * x.y + x.z * x.z + x.w * x.w;
#pragma unroll
    for (int d = 16; d > 0; d >>= 1) ss += __shfl_xor_sync(0xffffffffu, ss, d);
    const float rstd = rsqrtf(ss * (1.f / 128.f) + 1e-5f);
    const float4 g = *reinterpret_cast<const float4*>(g2 + base);
    const float4 wv = *reinterpret_cast<const float4*>(w + lane * 4);
    float4 r;
    r.x = x.x * rstd * wv.x / (1.f + expf(-g.x));
    r.y = x.y * rstd * wv.y / (1.f + expf(-g.y));
    r.z = x.z * rstd * wv.z / (1.f + expf(-g.z));
    r.w = x.w * rstd * wv.w / (1.f + expf(-g.w));
    *reinterpret_cast<float4*>(o + base) = r;
}

// ---------------- launch --------------------------------------------------------
extern "C" void kernel_launch(void* const* d_in, const int* in_sizes, int n_in,
                              void* d_out, int out_size) {
    const float* hs   = (const float*)d_in[0];
    const float* Wq   = (const float*)d_in[1];
    const float* Wk   = (const float*)d_in[2];
    const float* Wv   = (const float*)d_in[3];
    const float* cq   = (const float*)d_in[4];
    const float* ck   = (const float*)d_in[5];
    const float* cv   = (const float*)d_in[6];
    const float* Wb   = (const float*)d_in[7];
    const float* Wfa  = (const float*)d_in[8];
    const float* Wfb  = (const float*)d_in[9];
    const float* dtb  = (const float*)d_in[10];
    const float* Alog = (const float*)d_in[11];
    const float* Wga  = (const float*)d_in[12];
    const float* Wgb  = (const float*)d_in[13];
    const float* onw  = (const float*)d_in[14];
    const float* Wo   = (const float*)d_in[15];
    float* out = (float*)d_out;

    float *qp, *kp, *vp, *q, *k, *v, *eg, *g2, *o, *fa, *ga, *beta;
    float *wqR, *wkR, *wvR, *woR, *wfbR, *wgbR, *wfaR, *wgaR, *wbR;
    cudaGetSymbolAddress((void**)&qp, g_qp);
    cudaGetSymbolAddress((void**)&kp, g_kp);
    cudaGetSymbolAddress((void**)&vp, g_vp);
    cudaGetSymbolAddress((void**)&q,  g_q);
    cudaGetSymbolAddress((void**)&k,  g_k);
    cudaGetSymbolAddress((void**)&v,  g_v);
    cudaGetSymbolAddress((void**)&eg, g_eg);
    cudaGetSymbolAddress((void**)&g2, g_g2);
    cudaGetSymbolAddress((void**)&o,  g_o);
    cudaGetSymbolAddress((void**)&fa, g_fa);
    cudaGetSymbolAddress((void**)&ga, g_ga);
    cudaGetSymbolAddress((void**)&beta, g_beta);
    cudaGetSymbolAddress((void**)&wqR, g_wqR);
    cudaGetSymbolAddress((void**)&wkR, g_wkR);
    cudaGetSymbolAddress((void**)&wvR, g_wvR);
    cudaGetSymbolAddress((void**)&woR, g_woR);
    cudaGetSymbolAddress((void**)&wfbR, g_wfbR);
    cudaGetSymbolAddress((void**)&wgbR, g_wgbR);
    cudaGetSymbolAddress((void**)&wfaR, g_wfaR);
    cudaGetSymbolAddress((void**)&wgaR, g_wgaR);
    cudaGetSymbolAddress((void**)&wbR,  g_wbR);

    cudaFuncSetAttribute(mma_gemm, cudaFuncAttributeMaxDynamicSharedMemorySize, GEMM_SMEM);

    const dim3 blk(256);

    // rounded weight copies (+ padding for Wb)
    prep_w<<<(HID * PP + 255) / 256, blk>>>(Wq,  wqR,  PP,  PP,  HID * PP);
    prep_w<<<(HID * PP + 255) / 256, blk>>>(Wk,  wkR,  PP,  PP,  HID * PP);
    prep_w<<<(HID * PP + 255) / 256, blk>>>(Wv,  wvR,  PP,  PP,  HID * PP);
    prep_w<<<(PP * HID + 255) / 256, blk>>>(Wo,  woR,  HID, HID, PP * HID);
    prep_w<<<(HD * PP + 255) / 256,  blk>>>(Wfb, wfbR, PP,  PP,  HD * PP);
    prep_w<<<(HD * PP + 255) / 256,  blk>>>(Wgb, wgbR, PP,  PP,  HD * PP);
    prep_w<<<(HID * HD + 255) / 256, blk>>>(Wfa, wfaR, HD,  HD,  HID * HD);
    prep_w<<<(HID * HD + 255) / 256, blk>>>(Wga, wgaR, HD,  HD,  HID * HD);
    prep_w<<<(HID * HD + 255) / 256, blk>>>(Wb,  wbR,  NH,  HD,  HID * HD);

    // projections (tensor-core tf32)
    mma_gemm<<<dim3(32, 32), blk, GEMM_SMEM>>>(hs, wqR, qp, PP, PP, HID);
    mma_gemm<<<dim3(32, 32), blk, GEMM_SMEM>>>(hs, wkR, kp, PP, PP, HID);
    mma_gemm<<<dim3(32, 32), blk, GEMM_SMEM>>>(hs, wvR, vp, PP, PP, HID);
    mma_gemm<<<dim3(1, 32),  blk, GEMM_SMEM>>>(hs, wfaR, fa, HD, HD, HID);
    mma_gemm<<<dim3(1, 32),  blk, GEMM_SMEM>>>(hs, wgaR, ga, HD, HD, HID);
    mma_gemm<<<dim3(1, 32),  blk, GEMM_SMEM>>>(hs, wbR, beta, NH, HD, HID);

    // conv + silu (+ q scale 1/sqrt(128))
    conv_silu_k<<<TP / 256, blk>>>(qp, cq, q, 0.08838834764831845f);
    conv_silu_k<<<TP / 256, blk>>>(kp, ck, k, 1.f);
    conv_silu_k<<<TP / 256, blk>>>(vp, cv, v, 1.f);

    // gates
    beta_k<<<(TT * NH + 255) / 256, blk>>>(beta);
    mma_gemm<<<dim3(32, 32), blk, GEMM_SMEM>>>(fa, wfbR, eg, PP, PP, HD);
    gate_k<<<TP / 256, blk>>>(eg, dtb, Alog);
    mma_gemm<<<dim3(32, 32), blk, GEMM_SMEM>>>(ga, wgbR, g2, PP, PP, HD);

    // sequential KDA scan
    scan_k<<<dim3(4, NH), blk>>>(q, k, v, eg, beta, o);

    // gated rmsnorm + output projection
    rmsnorm_k<<<(TT * NH * 32) / 256, blk>>>(o, g2, onw);
    mma_gemm<<<dim3(16, 32), blk, GEMM_SMEM>>>(o, woR, out, HID, HID, PP);
}

// round 4
// speedup vs baseline: 1.9936x; 1.2813x over previous
#include <cuda_runtime.h>
#include <math.h>
#include <stdint.h>

#define TT   4096
#define HID  2048
#define NH   32
#define HD   128
#define PP   4096
#define TP   (TT * PP)

// ---------------- scratch (device globals; no allocations allowed) ----------
__device__ float g_hsr[TT * HID];
__device__ float g_qp[TP];
__device__ float g_kp[TP];
__device__ float g_vp[TP];
__device__ float g_q [TP];
__device__ float g_k [TP];
__device__ float g_v [TP];
__device__ float g_eg[TP];
__device__ float g_g2[TP];
__device__ float g_o [TP];
__device__ float g_fa[TT * HD];
__device__ float g_ga[TT * HD];
__device__ float g_beta[TT * NH];
// rounded (+padded) weights
__device__ float g_wqR[HID * PP];
__device__ float g_wkR[HID * PP];
__device__ float g_wvR[HID * PP];
__device__ float g_woR[PP * HID];
__device__ float g_wfbR[HD * PP];
__device__ float g_wgbR[HD * PP];
__device__ float g_wfaR[HID * HD];
__device__ float g_wgaR[HID * HD];
__device__ float g_wbR [HID * HD];   // Wb padded 32 -> 128 cols

// ---------------- helpers -----------------------------------------------------
__device__ __forceinline__ uint32_t smem_u32(const void* p) {
    uint32_t a;
    asm("{ .reg .u64 t; cvta.to.shared.u64 t, %1; cvt.u32.u64 %0, t; }" : "=r"(a) : "l"(p));
    return a;
}
__device__ __forceinline__ float rna_tf32(float x) {
    uint32_t o, i = __float_as_uint(x);
    asm("cvt.rna.tf32.f32 %0, %1;" : "=r"(o) : "r"(i));
    return __uint_as_float(o);
}
__device__ __forceinline__ void cp_async16(uint32_t dst, const float* src) {
    asm volatile("cp.async.cg.shared.global [%0], [%1], 16;\n"
                 :: "r"(dst), "l"(__cvta_generic_to_global(src)));
}
__device__ __forceinline__ void cp_commit() { asm volatile("cp.async.commit_group;\n" ::: "memory"); }

#define MMA_TF32(d, a, b)                                                      \
    asm volatile("mma.sync.aligned.m16n8k8.row.col.f32.tf32.tf32.f32 "        \
                 "{%0,%1,%2,%3}, {%4,%5,%6,%7}, {%8,%9}, {%0,%1,%2,%3};"      \
                 : "+f"((d)[0]), "+f"((d)[1]), "+f"((d)[2]), "+f"((d)[3])     \
                 : "r"((a)[0]), "r"((a)[1]), "r"((a)[2]), "r"((a)[3]),        \
                   "r"((b)[0]), "r"((b)[1]))

// ---------------- tf32 mma.sync GEMM ------------------------------------------
// C[M, Nvalid] = A[M,K] @ B[K,Npad]. Both A and B must be pre-rounded to tf32.
// CTA tile 128x128x32, 8 warps (warp tile 64x32), 3-stage cp.async pipeline.
#define BM 128
#define BN 128
#define BK 32
#define ASTR 36     // A smem row stride (floats): 36 % 32 == 4 -> frag-conflict-free
#define BSTR 136    // B smem row stride: 136 % 32 == 8 -> frag-conflict-free
#define A_STAGE (BM * ASTR)            // 4608 floats
#define B_STAGE (BK * BSTR)            // 4352 floats
#define STAGE_F (A_STAGE + B_STAGE)    // 8960 floats
#define NSTAGE 3
#define GEMM_SMEM (NSTAGE * STAGE_F * 4)   // 107520 bytes

__global__ __launch_bounds__(256, 2) void mma_gemm(const float* __restrict__ A,
                                                   const float* __restrict__ B,
                                                   float* __restrict__ C,
                                                   int Nvalid, int Npad, int K,
                                                   int round_out) {
    extern __shared__ float sm[];
    const uint32_t sb = smem_u32(sm);

    const int tid = threadIdx.x;
    const int wid = tid >> 5, lane = tid & 31;
    const int g = lane >> 2, tig = lane & 3;
    const int wm = (wid & 1) * 64, wn = (wid >> 1) * 32;
    const int bm = blockIdx.y * BM, bn = blockIdx.x * BN;
    const int NC = K >> 5;

    // A staging: quad q = tid + 256j -> row q>>3 (0..127), kq q&7 (0..7)
    const int arow = tid >> 3, akq = tid & 7;
    // B staging: quad q = tid + 256j -> row q>>5 (0..31), nq q&31
    const int brow = tid >> 5, bnq = tid & 31;

    float acc[4][4][4];
#pragma unroll
    for (int i = 0; i < 4; i++)
#pragma unroll
        for (int j = 0; j < 4; j++)
#pragma unroll
            for (int r = 0; r < 4; r++) acc[i][j][r] = 0.f;

#define LOADST(chunk, stage) do {                                               \
        const int kb = (chunk) * BK;                                            \
        const uint32_t sA = sb + (stage) * STAGE_F * 4;                         \
        const uint32_t sB = sA + A_STAGE * 4;                                   \
        _Pragma("unroll")                                                       \
        for (int j = 0; j < 4; j++) {                                           \
            const int r = arow + 32 * j;                                        \
            cp_async16(sA + (r * ASTR + akq * 4) * 4,                           \
                       A + (size_t)(bm + r) * K + kb + akq * 4);                \
        }                                                                       \
        _Pragma("unroll")                                                       \
        for (int j = 0; j < 4; j++) {                                           \
            const int r = brow + 8 * j;                                         \
            cp_async16(sB + (r * BSTR + bnq * 4) * 4,                           \
                       B + (size_t)(kb + r) * Npad + bn + bnq * 4);             \
        }                                                                       \
        cp_commit();                                                            \
    } while (0)

    // prologue: chunks 0 and 1
    LOADST(0, 0);
    if (NC > 1) LOADST(1, 1);

    for (int i = 0; i < NC; i++) {
        if (i + 2 < NC) asm volatile("cp.async.wait_group 1;\n" ::: "memory");
        else            asm volatile("cp.async.wait_group 0;\n" ::: "memory");
        __syncthreads();
        if (i + 2 < NC) {
            int st = i + 2;
            st = st - (st / NSTAGE) * NSTAGE;
            LOADST(i + 2, st);
        }

        const int stage = i - (i / NSTAGE) * NSTAGE;
        const float* ab = sm + stage * STAGE_F;
        const float* bb = ab + A_STAGE;
#pragma unroll
        for (int s = 0; s < 4; s++) {
            uint32_t af[4][4], bf[4][2];
            const int kk = 8 * s + tig;
#pragma unroll
            for (int mf = 0; mf < 4; mf++) {
                const float* p = ab + (wm + 16 * mf + g) * ASTR + kk;
                af[mf][0] = __float_as_uint(p[0]);
                af[mf][1] = __float_as_uint(p[8 * ASTR]);
                af[mf][2] = __float_as_uint(p[4]);
                af[mf][3] = __float_as_uint(p[8 * ASTR + 4]);
            }
            const float* brow0 = bb + kk * BSTR + wn;
#pragma unroll
            for (int nf = 0; nf < 4; nf++) {
                bf[nf][0] = __float_as_uint(brow0[8 * nf + g]);
                bf[nf][1] = __float_as_uint(brow0[8 * nf + g + 4 * BSTR]);
            }
#pragma unroll
            for (int mf = 0; mf < 4; mf++)
#pragma unroll
                for (int nf = 0; nf < 4; nf++)
                    MMA_TF32(acc[mf][nf], af[mf], bf[nf]);
        }
    }

    // epilogue
#pragma unroll
    for (int mf = 0; mf < 4; mf++) {
        const int row0 = bm + wm + 16 * mf + g;
#pragma unroll
        for (int nf = 0; nf < 4; nf++) {
            const int col = bn + wn + 8 * nf + 2 * tig;
            if (col < Nvalid) {
                float4 vals = make_float4(acc[mf][nf][0], acc[mf][nf][1],
                                          acc[mf][nf][2], acc[mf][nf][3]);
                if (round_out) {
                    vals.x = rna_tf32(vals.x); vals.y = rna_tf32(vals.y);
                    vals.z = rna_tf32(vals.z); vals.w = rna_tf32(vals.w);
                }
                *reinterpret_cast<float2*>(C + (size_t)row0 * Nvalid + col) =
                    make_float2(vals.x, vals.y);
                *reinterpret_cast<float2*>(C + (size_t)(row0 + 8) * Nvalid + col) =
                    make_float2(vals.z, vals.w);
            }
        }
    }
}

// ---------------- weight/activation prep: vectorized tf32 rounding ----------
__global__ void prep_w4(const float4* __restrict__ in, float4* __restrict__ out, int n4) {
    const int i = blockIdx.x * 256 + threadIdx.x;
    if (i >= n4) return;
    float4 v = in[i];
    v.x = rna_tf32(v.x); v.y = rna_tf32(v.y);
    v.z = rna_tf32(v.z); v.w = rna_tf32(v.w);
    out[i] = v;
}

// scalar prep with right-pad (for Wb 32 -> 128 cols)
__global__ void prep_w(const float* __restrict__ in, float* __restrict__ out,
                       int N, int Npad, int total) {
    const int idx = blockIdx.x * 256 + threadIdx.x;
    if (idx >= total) return;
    const int k = idx / Npad, n = idx % Npad;
    out[idx] = (n < N) ? rna_tf32(in[(size_t)k * N + n]) : 0.f;
}

// ---------------- depthwise causal conv (K=4) + SiLU (+ scale) --------------
__global__ __launch_bounds__(256) void conv_silu_k(const float* __restrict__ x,
                                                   const float* __restrict__ w,
                                                   float* __restrict__ y, float scale) {
    const int idx = blockIdx.x * 256 + threadIdx.x;
    const int t = idx >> 12;
    const int p = idx & (PP - 1);
    const float4 wv = *reinterpret_cast<const float4*>(w + p * 4);
    float acc = x[idx] * wv.w;
    if (t >= 1) acc += x[idx - PP] * wv.z;
    if (t >= 2) acc += x[idx - 2 * PP] * wv.y;
    if (t >= 3) acc += x[idx - 3 * PP] * wv.x;
    const float sg = 1.f / (1.f + expf(-acc));
    y[idx] = acc * sg * scale;
}

__global__ void beta_k(float* __restrict__ b) {
    const int idx = blockIdx.x * 256 + threadIdx.x;
    if (idx < TT * NH) b[idx] = 2.f / (1.f + expf(-b[idx]));
}

__global__ __launch_bounds__(256) void gate_k(float* __restrict__ g,
                                              const float* __restrict__ dt_bias,
                                              const float* __restrict__ A_log) {
    const int idx = blockIdx.x * 256 + threadIdx.x;
    const int p = idx & (PP - 1);
    const int h = p >> 7;
    const float a = expf(A_log[h]);
    const float x = g[idx] + dt_bias[p];
    const float sg = 1.f / (1.f + expf(-a * x));
    g[idx] = expf(-5.f * sg);
}

// ---------------- KDA scan ----------------------------------------------------
struct Step { float k[16], q[16], e[16]; float v, b; };

__device__ __forceinline__ void ld16(float* d, const float* s) {
    float4 v0 = *reinterpret_cast<const float4*>(s);
    float4 v1 = *reinterpret_cast<const float4*>(s + 4);
    float4 v2 = *reinterpret_cast<const float4*>(s + 8);
    float4 v3 = *reinterpret_cast<const float4*>(s + 12);
    d[0] = v0.x; d[1] = v0.y; d[2]  = v0.z; d[3]  = v0.w;
    d[4] = v1.x; d[5] = v1.y; d[6]  = v1.z; d[7]  = v1.w;
    d[8] = v2.x; d[9] = v2.y; d[10] = v2.z; d[11] = v2.w;
    d[12] = v3.x; d[13] = v3.y; d[14] = v3.z; d[15] = v3.w;
}

__device__ __forceinline__ void fetch_step(Step& st, int t, int off_kqe, int off_v, int h,
                                           const float* __restrict__ q,
                                           const float* __restrict__ k,
                                           const float* __restrict__ v,
                                           const float* __restrict__ eg,
                                           const float* __restrict__ beta) {
    const int base = t * PP;
    ld16(st.k, k + base + off_kqe);
    ld16(st.q, q + base + off_kqe);
    ld16(st.e, eg + base + off_kqe);
    st.v = v[base + off_v];
    st.b = beta[t * NH + h];
}

__device__ __forceinline__ void do_step(float* S, const Step& st,
                                        float* __restrict__ o, int t, int off_v, int s) {
    float p0 = 0.f, p1 = 0.f;
#pragma unroll
    for (int r = 0; r < 16; r += 2) {
        S[r]     *= st.e[r];     p0 += S[r]     * st.k[r];
        S[r + 1] *= st.e[r + 1]; p1 += S[r + 1] * st.k[r + 1];
    }
    float part = p0 + p1;
    part += __shfl_xor_sync(0xffffffffu, part, 1);
    part += __shfl_xor_sync(0xffffffffu, part, 2);
    part += __shfl_xor_sync(0xffffffffu, part, 4);
    const float u = st.b * (st.v - part);
    float o0 = 0.f, o1 = 0.f;
#pragma unroll
    for (int r = 0; r < 16; r += 2) {
        S[r]     += st.k[r] * u;     o0 += st.q[r]     * S[r];
        S[r + 1] += st.k[r + 1] * u; o1 += st.q[r + 1] * S[r + 1];
    }
    float po = o0 + o1;
    po += __shfl_xor_sync(0xffffffffu, po, 1);
    po += __shfl_xor_sync(0xffffffffu, po, 2);
    po += __shfl_xor_sync(0xffffffffu, po, 4);
    if (s == 0) o[t * PP + off_v] = po;
}

__global__ __launch_bounds__(256) void scan_k(const float* __restrict__ q,
                                              const float* __restrict__ k,
                                              const float* __restrict__ v,
                                              const float* __restrict__ eg,
                                              const float* __restrict__ beta,
                                              float* __restrict__ o) {
    const int h = blockIdx.y;
    const int jl = threadIdx.x >> 3;
    const int s = threadIdx.x & 7;
    const int j = blockIdx.x * 32 + jl;
    const int off_kqe = h * HD + s * 16;
    const int off_v = h * HD + j;

    float S[16];
#pragma unroll
    for (int r = 0; r < 16; r++) S[r] = 0.f;

    Step A, B;
    fetch_step(A, 0, off_kqe, off_v, h, q, k, v, eg, beta);
    for (int t = 0; t < TT; t += 2) {
        fetch_step(B, t + 1, off_kqe, off_v, h, q, k, v, eg, beta);
        do_step(S, A, o, t, off_v, s);
        const int t2 = (t + 2 < TT) ? (t + 2) : (TT - 1);
        fetch_step(A, t2, off_kqe, off_v, h, q, k, v, eg, beta);
        do_step(S, B, o, t + 1, off_v, s);
    }
}

// ---------------- gated RMSNorm (rounds output for Wo GEMM) -------------------
__global__ __launch_bounds__(256) void rmsnorm_k(float* __restrict__ o,
                                                 const float* __restrict__ g2,
                                                 const float* __restrict__ w) {
    const int warp = (blockIdx.x * blockDim.x + threadIdx.x) >> 5;
    const int lane = threadIdx.x & 31;
    if (warp >= TT * NH) return;
    const int base = warp * HD + lane * 4;
    float4 x = *reinterpret_cast<const float4*>(o + base);
    float ss = x.x * x.x + x.y * x.y + x.z * x.z + x.w * x.w;
#pragma unroll
    for (int d = 16; d > 0; d >>= 1) ss += __shfl_xor_sync(0xffffffffu, ss, d);
    const float rstd = rsqrtf(ss * (1.f / 128.f) + 1e-5f);
    const float4 g = *reinterpret_cast<const float4*>(g2 + base);
    const float4 wv = *reinterpret_cast<const float4*>(w + lane * 4);
    float4 r;
    r.x = rna_tf32(x.x * rstd * wv.x / (1.f + expf(-g.x)));
    r.y = rna_tf32(x.y * rstd * wv.y / (1.f + expf(-g.y)));
    r.z = rna_tf32(x.z * rstd * wv.z / (1.f + expf(-g.z)));
    r.w = rna_tf32(x.w * rstd * wv.w / (1.f + expf(-g.w)));
    *reinterpret_cast<float4*>(o + base) = r;
}

// ---------------- launch --------------------------------------------------------
extern "C" void kernel_launch(void* const* d_in, const int* in_sizes, int n_in,
                              void* d_out, int out_size) {
    const float* hs   = (const float*)d_in[0];
    const float* Wq   = (const float*)d_in[1];
    const float* Wk   = (const float*)d_in[2];
    const float* Wv   = (const float*)d_in[3];
    const float* cq   = (const float*)d_in[4];
    const float* ck   = (const float*)d_in[5];
    const float* cv   = (const float*)d_in[6];
    const float* Wb   = (const float*)d_in[7];
    const float* Wfa  = (const float*)d_in[8];
    const float* Wfb  = (const float*)d_in[9];
    const float* dtb  = (const float*)d_in[10];
    const float* Alog = (const float*)d_in[11];
    const float* Wga  = (const float*)d_in[12];
    const float* Wgb  = (const float*)d_in[13];
    const float* onw  = (const float*)d_in[14];
    const float* Wo   = (const float*)d_in[15];
    float* out = (float*)d_out;

    float *hsr, *qp, *kp, *vp, *q, *k, *v, *eg, *g2, *o, *fa, *ga, *beta;
    float *wqR, *wkR, *wvR, *woR, *wfbR, *wgbR, *wfaR, *wgaR, *wbR;
    cudaGetSymbolAddress((void**)&hsr, g_hsr);
    cudaGetSymbolAddress((void**)&qp, g_qp);
    cudaGetSymbolAddress((void**)&kp, g_kp);
    cudaGetSymbolAddress((void**)&vp, g_vp);
    cudaGetSymbolAddress((void**)&q,  g_q);
    cudaGetSymbolAddress((void**)&k,  g_k);
    cudaGetSymbolAddress((void**)&v,  g_v);
    cudaGetSymbolAddress((void**)&eg, g_eg);
    cudaGetSymbolAddress((void**)&g2, g_g2);
    cudaGetSymbolAddress((void**)&o,  g_o);
    cudaGetSymbolAddress((void**)&fa, g_fa);
    cudaGetSymbolAddress((void**)&ga, g_ga);
    cudaGetSymbolAddress((void**)&beta, g_beta);
    cudaGetSymbolAddress((void**)&wqR, g_wqR);
    cudaGetSymbolAddress((void**)&wkR, g_wkR);
    cudaGetSymbolAddress((void**)&wvR, g_wvR);
    cudaGetSymbolAddress((void**)&woR, g_woR);
    cudaGetSymbolAddress((void**)&wfbR, g_wfbR);
    cudaGetSymbolAddress((void**)&wgbR, g_wgbR);
    cudaGetSymbolAddress((void**)&wfaR, g_wfaR);
    cudaGetSymbolAddress((void**)&wgaR, g_wgaR);
    cudaGetSymbolAddress((void**)&wbR,  g_wbR);

    cudaFuncSetAttribute(mma_gemm, cudaFuncAttributeMaxDynamicSharedMemorySize, GEMM_SMEM);

    const dim3 blk(256);

    // launches 1-5: activation + big-weight prep (launch 6 = profiled GEMM)
    prep_w4<<<(TT * HID / 4 + 255) / 256, blk>>>((const float4*)hs, (float4*)hsr, TT * HID / 4);
    prep_w4<<<(HID * PP / 4 + 255) / 256, blk>>>((const float4*)Wq, (float4*)wqR, HID * PP / 4);
    prep_w4<<<(HID * PP / 4 + 255) / 256, blk>>>((const float4*)Wk, (float4*)wkR, HID * PP / 4);
    prep_w4<<<(HID * PP / 4 + 255) / 256, blk>>>((const float4*)Wv, (float4*)wvR, HID * PP / 4);
    prep_w4<<<(PP * HID / 4 + 255) / 256, blk>>>((const float4*)Wo, (float4*)woR, PP * HID / 4);

    // launch 6: profiled big GEMM
    mma_gemm<<<dim3(32, 32), blk, GEMM_SMEM>>>(hsr, wqR, qp, PP, PP, HID, 0);
    mma_gemm<<<dim3(32, 32), blk, GEMM_SMEM>>>(hsr, wkR, kp, PP, PP, HID, 0);
    mma_gemm<<<dim3(32, 32), blk, GEMM_SMEM>>>(hsr, wvR, vp, PP, PP, HID, 0);

    // remaining weight prep
    prep_w4<<<(HD * PP / 4 + 255) / 256,  blk>>>((const float4*)Wfb, (float4*)wfbR, HD * PP / 4);
    prep_w4<<<(HD * PP / 4 + 255) / 256,  blk>>>((const float4*)Wgb, (float4*)wgbR, HD * PP / 4);
    prep_w4<<<(HID * HD / 4 + 255) / 256, blk>>>((const float4*)Wfa, (float4*)wfaR, HID * HD / 4);
    prep_w4<<<(HID * HD / 4 + 255) / 256, blk>>>((const float4*)Wga, (float4*)wgaR, HID * HD / 4);
    prep_w<<<(HID * HD + 255) / 256, blk>>>(Wb, wbR, NH, HD, HID * HD);

    // small-N GEMMs (fa/ga rounded in epilogue; they feed further GEMMs)
    mma_gemm<<<dim3(1, 32), blk, GEMM_SMEM>>>(hsr, wfaR, fa, HD, HD, HID, 1);
    mma_gemm<<<dim3(1, 32), blk, GEMM_SMEM>>>(hsr, wgaR, ga, HD, HD, HID, 1);
    mma_gemm<<<dim3(1, 32), blk, GEMM_SMEM>>>(hsr, wbR, beta, NH, HD, HID, 0);

    // conv + silu (+ q scale 1/sqrt(128))
    conv_silu_k<<<TP / 256, blk>>>(qp, cq, q, 0.08838834764831845f);
    conv_silu_k<<<TP / 256, blk>>>(kp, ck, k, 1.f);
    conv_silu_k<<<TP / 256, blk>>>(vp, cv, v, 1.f);

    // gates
    beta_k<<<(TT * NH + 255) / 256, blk>>>(beta);
    mma_gemm<<<dim3(32, 32), blk, GEMM_SMEM>>>(fa, wfbR, eg, PP, PP, HD, 0);
    gate_k<<<TP / 256, blk>>>(eg, dtb, Alog);
    mma_gemm<<<dim3(32, 32), blk, GEMM_SMEM>>>(ga, wgbR, g2, PP, PP, HD, 0);

    // sequential KDA scan
    scan_k<<<dim3(4, NH), blk>>>(q, k, v, eg, beta, o);

    // gated rmsnorm (rounds o for Wo GEMM) + output projection
    rmsnorm_k<<<(TT * NH * 32) / 256, blk>>>(o, g2, onw);
    mma_gemm<<<dim3(16, 32), blk, GEMM_SMEM>>>(o, woR, out, HID, HID, PP, 0);
}

// round 5
// speedup vs baseline: 2.0046x; 1.0055x over previous
#include <cuda_runtime.h>
#include <math.h>
#include <stdint.h>

#define TT   4096
#define HID  2048
#define NH   32
#define HD   128
#define PP   4096
#define TP   (TT * PP)
#define NQKV 12288    // 3*PP
#define NFAB 384      // fa(128) | ga(128) | beta(32 pad->128)

// ---------------- scratch (device globals; no allocations allowed) ----------
__device__ float g_hsr[TT * HID];
__device__ float g_qkvp[TT * NQKV];
__device__ float g_q [TP];
__device__ float g_k [TP];
__device__ float g_v [TP];
__device__ float g_eg[TP];
__device__ float g_g2[TP];
__device__ float g_o [TP];
__device__ float g_fab[TT * NFAB];
__device__ float g_beta[TT * NH];
// rounded (+padded/concatenated) weights
__device__ float g_wqkvR[HID * NQKV];
__device__ float g_wfabR[HID * NFAB];
__device__ float g_wfbR[HD * PP];
__device__ float g_wgbR[HD * PP];
__device__ float g_woR[PP * HID];

// ---------------- helpers -----------------------------------------------------
__device__ __forceinline__ uint32_t smem_u32(const void* p) {
    uint32_t a;
    asm("{ .reg .u64 t; cvta.to.shared.u64 t, %1; cvt.u32.u64 %0, t; }" : "=r"(a) : "l"(p));
    return a;
}
__device__ __forceinline__ float rna_tf32(float x) {
    uint32_t o, i = __float_as_uint(x);
    asm("cvt.rna.tf32.f32 %0, %1;" : "=r"(o) : "r"(i));
    return __uint_as_float(o);
}
__device__ __forceinline__ void cp_async16(uint32_t dst, const float* src) {
    asm volatile("cp.async.cg.shared.global [%0], [%1], 16;\n"
                 :: "r"(dst), "l"(__cvta_generic_to_global(src)));
}
__device__ __forceinline__ void cp_commit() { asm volatile("cp.async.commit_group;\n" ::: "memory"); }

#define MMA_TF32(d, a, b)                                                      \
    asm volatile("mma.sync.aligned.m16n8k8.row.col.f32.tf32.tf32.f32 "        \
                 "{%0,%1,%2,%3}, {%4,%5,%6,%7}, {%8,%9}, {%0,%1,%2,%3};"      \
                 : "+f"((d)[0]), "+f"((d)[1]), "+f"((d)[2]), "+f"((d)[3])     \
                 : "r"((a)[0]), "r"((a)[1]), "r"((a)[2]), "r"((a)[3]),        \
                   "r"((b)[0]), "r"((b)[1]))

// ---------------- tf32 mma.sync GEMM ------------------------------------------
// C[M, :Nvalid] (stride ldc) = A[M,K] (stride lda) @ B[K, :] (stride ldb).
// All inputs pre-rounded tf32. CTA tile 128x128x32, 8 warps, 3-stage cp.async.
#define BM 128
#define BN 128
#define BK 32
#define ASTR 36
#define BSTR 136
#define A_STAGE (BM * ASTR)
#define B_STAGE (BK * BSTR)
#define STAGE_F (A_STAGE + B_STAGE)
#define NSTAGE 3
#define GEMM_SMEM (NSTAGE * STAGE_F * 4)

__global__ __launch_bounds__(256, 2) void mma_gemm(const float* __restrict__ A, int lda,
                                                   const float* __restrict__ B, int ldb,
                                                   float* __restrict__ C, int ldc,
                                                   int Nvalid, int K, int round_limit) {
    extern __shared__ float sm[];
    const uint32_t sb = smem_u32(sm);

    const int tid = threadIdx.x;
    const int wid = tid >> 5, lane = tid & 31;
    const int g = lane >> 2, tig = lane & 3;
    const int wm = (wid & 1) * 64, wn = (wid >> 1) * 32;
    const int bm = blockIdx.y * BM, bn = blockIdx.x * BN;
    const int NC = K >> 5;

    const int arow = tid >> 3, akq = tid & 7;
    const int brow = tid >> 5, bnq = tid & 31;

    float acc[4][4][4];
#pragma unroll
    for (int i = 0; i < 4; i++)
#pragma unroll
        for (int j = 0; j < 4; j++)
#pragma unroll
            for (int r = 0; r < 4; r++) acc[i][j][r] = 0.f;

#define LOADST(chunk, stage) do {                                               \
        const int kb = (chunk) * BK;                                            \
        const uint32_t sA = sb + (stage) * STAGE_F * 4;                         \
        const uint32_t sB = sA + A_STAGE * 4;                                   \
        _Pragma("unroll")                                                       \
        for (int j = 0; j < 4; j++) {                                           \
            const int r = arow + 32 * j;                                        \
            cp_async16(sA + (r * ASTR + akq * 4) * 4,                           \
                       A + (size_t)(bm + r) * lda + kb + akq * 4);              \
        }                                                                       \
        _Pragma("unroll")                                                       \
        for (int j = 0; j < 4; j++) {                                           \
            const int r = brow + 8 * j;                                         \
            cp_async16(sB + (r * BSTR + bnq * 4) * 4,                           \
                       B + (size_t)(kb + r) * ldb + bn + bnq * 4);              \
        }                                                                       \
        cp_commit();                                                            \
    } while (0)

    LOADST(0, 0);
    if (NC > 1) LOADST(1, 1);

    for (int i = 0; i < NC; i++) {
        if (i + 2 < NC) asm volatile("cp.async.wait_group 1;\n" ::: "memory");
        else            asm volatile("cp.async.wait_group 0;\n" ::: "memory");
        __syncthreads();
        if (i + 2 < NC) {
            int st = i + 2;
            st = st - (st / NSTAGE) * NSTAGE;
            LOADST(i + 2, st);
        }

        const int stage = i - (i / NSTAGE) * NSTAGE;
        const float* ab = sm + stage * STAGE_F;
        const float* bb = ab + A_STAGE;
#pragma unroll
        for (int s = 0; s < 4; s++) {
            uint32_t af[4][4], bf[4][2];
            const int kk = 8 * s + tig;
#pragma unroll
            for (int mf = 0; mf < 4; mf++) {
                const float* p = ab + (wm + 16 * mf + g) * ASTR + kk;
                af[mf][0] = __float_as_uint(p[0]);
                af[mf][1] = __float_as_uint(p[8 * ASTR]);
                af[mf][2] = __float_as_uint(p[4]);
                af[mf][3] = __float_as_uint(p[8 * ASTR + 4]);
            }
            const float* brow0 = bb + kk * BSTR + wn;
#pragma unroll
            for (int nf = 0; nf < 4; nf++) {
                bf[nf][0] = __float_as_uint(brow0[8 * nf + g]);
                bf[nf][1] = __float_as_uint(brow0[8 * nf + g + 4 * BSTR]);
            }
#pragma unroll
            for (int mf = 0; mf < 4; mf++)
#pragma unroll
                for (int nf = 0; nf < 4; nf++)
                    MMA_TF32(acc[mf][nf], af[mf], bf[nf]);
        }
    }

    // epilogue
#pragma unroll
    for (int mf = 0; mf < 4; mf++) {
        const int row0 = bm + wm + 16 * mf + g;
#pragma unroll
        for (int nf = 0; nf < 4; nf++) {
            const int col = bn + wn + 8 * nf + 2 * tig;
            if (col < Nvalid) {
                float4 vals = make_float4(acc[mf][nf][0], acc[mf][nf][1],
                                          acc[mf][nf][2], acc[mf][nf][3]);
                if (col < round_limit) {
                    vals.x = rna_tf32(vals.x); vals.y = rna_tf32(vals.y);
                    vals.z = rna_tf32(vals.z); vals.w = rna_tf32(vals.w);
                }
                *reinterpret_cast<float2*>(C + (size_t)row0 * ldc + col) =
                    make_float2(vals.x, vals.y);
                *reinterpret_cast<float2*>(C + (size_t)(row0 + 8) * ldc + col) =
                    make_float2(vals.z, vals.w);
            }
        }
    }
}

// ---------------- prep kernels ------------------------------------------------
__global__ void prep_w4(const float4* __restrict__ in, float4* __restrict__ out, int n4) {
    const int i = blockIdx.x * 256 + threadIdx.x;
    if (i >= n4) return;
    float4 v = in[i];
    v.x = rna_tf32(v.x); v.y = rna_tf32(v.y);
    v.z = rna_tf32(v.z); v.w = rna_tf32(v.w);
    out[i] = v;
}

// concat Wq|Wk|Wv -> [HID, 12288], tf32-rounded
__global__ void prep_wqkv(const float4* __restrict__ wq, const float4* __restrict__ wk,
                          const float4* __restrict__ wv, float4* __restrict__ out, int total4) {
    const int i = blockIdx.x * 256 + threadIdx.x;
    if (i >= total4) return;
    const int n4 = i % (NQKV / 4);
    const int row = i / (NQKV / 4);
    const int seg = n4 >> 10;                  // 0,1,2
    const int off = row * (PP / 4) + (n4 & 1023);
    float4 v = (seg == 0) ? wq[off] : (seg == 1) ? wk[off] : wv[off];
    v.x = rna_tf32(v.x); v.y = rna_tf32(v.y);
    v.z = rna_tf32(v.z); v.w = rna_tf32(v.w);
    out[i] = v;
}

// concat Wfa|Wga|Wb(pad) -> [HID, 384], tf32-rounded
__global__ void prep_wfab(const float4* __restrict__ wfa, const float4* __restrict__ wga,
                          const float4* __restrict__ wb, float4* __restrict__ out, int total4) {
    const int i = blockIdx.x * 256 + threadIdx.x;
    if (i >= total4) return;
    const int n4 = i % (NFAB / 4);             // 0..95
    const int row = i / (NFAB / 4);
    float4 v = make_float4(0.f, 0.f, 0.f, 0.f);
    if (n4 < 32)       v = wfa[row * 32 + n4];
    else if (n4 < 64)  v = wga[row * 32 + (n4 - 32)];
    else if (n4 < 72)  v = wb[row * 8 + (n4 - 64)];
    v.x = rna_tf32(v.x); v.y = rna_tf32(v.y);
    v.z = rna_tf32(v.z); v.w = rna_tf32(v.w);
    out[i] = v;
}

// ---------------- depthwise causal conv (K=4) + SiLU (+ scale) --------------
// x is a column-slice of qkvp: row stride NQKV; y compact [T, PP]
__global__ __launch_bounds__(256) void conv_silu_k(const float* __restrict__ x,
                                                   const float* __restrict__ w,
                                                   float* __restrict__ y, float scale) {
    const int idx = blockIdx.x * 256 + threadIdx.x;
    const int t = idx >> 12;
    const int p = idx & (PP - 1);
    const size_t xi = (size_t)t * NQKV + p;
    const float4 wv = *reinterpret_cast<const float4*>(w + p * 4);
    float acc = x[xi] * wv.w;
    if (t >= 1) acc += x[xi - NQKV] * wv.z;
    if (t >= 2) acc += x[xi - 2 * NQKV] * wv.y;
    if (t >= 3) acc += x[xi - 3 * NQKV] * wv.x;
    const float sg = 1.f / (1.f + expf(-acc));
    y[idx] = acc * sg * scale;
}

__global__ void beta_k(const float* __restrict__ fab, float* __restrict__ b) {
    const int idx = blockIdx.x * 256 + threadIdx.x;
    if (idx >= TT * NH) return;
    const int t = idx >> 5, h = idx & 31;
    const float x = fab[(size_t)t * NFAB + 256 + h];
    b[idx] = 2.f / (1.f + expf(-x));
}

__global__ __launch_bounds__(256) void gate_k(float* __restrict__ g,
                                              const float* __restrict__ dt_bias,
                                              const float* __restrict__ A_log) {
    const int idx = blockIdx.x * 256 + threadIdx.x;
    const int p = idx & (PP - 1);
    const int h = p >> 7;
    const float a = expf(A_log[h]);
    const float x = g[idx] + dt_bias[p];
    const float sg = 1.f / (1.f + expf(-a * x));
    g[idx] = expf(-5.f * sg);
}

// ---------------- KDA scan ----------------------------------------------------
struct Step { float k[16], q[16], e[16]; float v, b; };

__device__ __forceinline__ void ld16(float* d, const float* s) {
    float4 v0 = *reinterpret_cast<const float4*>(s);
    float4 v1 = *reinterpret_cast<const float4*>(s + 4);
    float4 v2 = *reinterpret_cast<const float4*>(s + 8);
    float4 v3 = *reinterpret_cast<const float4*>(s + 12);
    d[0] = v0.x; d[1] = v0.y; d[2]  = v0.z; d[3]  = v0.w;
    d[4] = v1.x; d[5] = v1.y; d[6]  = v1.z; d[7]  = v1.w;
    d[8] = v2.x; d[9] = v2.y; d[10] = v2.z; d[11] = v2.w;
    d[12] = v3.x; d[13] = v3.y; d[14] = v3.z; d[15] = v3.w;
}

__device__ __forceinline__ void fetch_step(Step& st, int t, int off_kqe, int off_v, int h,
                                           const float* __restrict__ q,
                                           const float* __restrict__ k,
                                           const float* __restrict__ v,
                                           const float* __restrict__ eg,
                                           const float* __restrict__ beta) {
    const int base = t * PP;
    ld16(st.k, k + base + off_kqe);
    ld16(st.q, q + base + off_kqe);
    ld16(st.e, eg + base + off_kqe);
    st.v = v[base + off_v];
    st.b = beta[t * NH + h];
}

__device__ __forceinline__ void do_step(float* S, const Step& st,
                                        float* __restrict__ o, int t, int off_v, int s) {
    float p0 = 0.f, p1 = 0.f;
#pragma unroll
    for (int r = 0; r < 16; r += 2) {
        S[r]     *= st.e[r];     p0 += S[r]     * st.k[r];
        S[r + 1] *= st.e[r + 1]; p1 += S[r + 1] * st.k[r + 1];
    }
    float part = p0 + p1;
    part += __shfl_xor_sync(0xffffffffu, part, 1);
    part += __shfl_xor_sync(0xffffffffu, part, 2);
    part += __shfl_xor_sync(0xffffffffu, part, 4);
    const float u = st.b * (st.v - part);
    float o0 = 0.f, o1 = 0.f;
#pragma unroll
    for (int r = 0; r < 16; r += 2) {
        S[r]     += st.k[r] * u;     o0 += st.q[r]     * S[r];
        S[r + 1] += st.k[r + 1] * u; o1 += st.q[r + 1] * S[r + 1];
    }
    float po = o0 + o1;
    po += __shfl_xor_sync(0xffffffffu, po, 1);
    po += __shfl_xor_sync(0xffffffffu, po, 2);
    po += __shfl_xor_sync(0xffffffffu, po, 4);
    if (s == 0) o[t * PP + off_v] = po;
}

__global__ __launch_bounds__(256) void scan_k(const float* __restrict__ q,
                                              const float* __restrict__ k,
                                              const float* __restrict__ v,
                                              const float* __restrict__ eg,
                                              const float* __restrict__ beta,
                                              float* __restrict__ o) {
    const int h = blockIdx.y;
    const int jl = threadIdx.x >> 3;
    const int s = threadIdx.x & 7;
    const int j = blockIdx.x * 32 + jl;
    const int off_kqe = h * HD + s * 16;
    const int off_v = h * HD + j;

    float S[16];
#pragma unroll
    for (int r = 0; r < 16; r++) S[r] = 0.f;

    Step A, B;
    fetch_step(A, 0, off_kqe, off_v, h, q, k, v, eg, beta);
    for (int t = 0; t < TT; t += 2) {
        fetch_step(B, t + 1, off_kqe, off_v, h, q, k, v, eg, beta);
        do_step(S, A, o, t, off_v, s);
        const int t2 = (t + 2 < TT) ? (t + 2) : (TT - 1);
        fetch_step(A, t2, off_kqe, off_v, h, q, k, v, eg, beta);
        do_step(S, B, o, t + 1, off_v, s);
    }
}

// ---------------- gated RMSNorm (rounds output for Wo GEMM) -------------------
__global__ __launch_bounds__(256) void rmsnorm_k(float* __restrict__ o,
                                                 const float* __restrict__ g2,
                                                 const float* __restrict__ w) {
    const int warp = (blockIdx.x * blockDim.x + threadIdx.x) >> 5;
    const int lane = threadIdx.x & 31;
    if (warp >= TT * NH) return;
    const int base = warp * HD + lane * 4;
    float4 x = *reinterpret_cast<const float4*>(o + base);
    float ss = x.x * x.x + x.y * x.y + x.z * x.z + x.w * x.w;
#pragma unroll
    for (int d = 16; d > 0; d >>= 1) ss += __shfl_xor_sync(0xffffffffu, ss, d);
    const float rstd = rsqrtf(ss * (1.f / 128.f) + 1e-5f);
    const float4 g = *reinterpret_cast<const float4*>(g2 + base);
    const float4 wv = *reinterpret_cast<const float4*>(w + lane * 4);
    float4 r;
    r.x = rna_tf32(x.x * rstd * wv.x / (1.f + expf(-g.x)));
    r.y = rna_tf32(x.y * rstd * wv.y / (1.f + expf(-g.y)));
    r.z = rna_tf32(x.z * rstd * wv.z / (1.f + expf(-g.z)));
    r.w = rna_tf32(x.w * rstd * wv.w / (1.f + expf(-g.w)));
    *reinterpret_cast<float4*>(o + base) = r;
}

// ---------------- launch --------------------------------------------------------
extern "C" void kernel_launch(void* const* d_in, const int* in_sizes, int n_in,
                              void* d_out, int out_size) {
    const float* hs   = (const float*)d_in[0];
    const float* Wq   = (const float*)d_in[1];
    const float* Wk   = (const float*)d_in[2];
    const float* Wv   = (const float*)d_in[3];
    const float* cq   = (const float*)d_in[4];
    const float* ck   = (const float*)d_in[5];
    const float* cv   = (const float*)d_in[6];
    const float* Wb   = (const float*)d_in[7];
    const float* Wfa  = (const float*)d_in[8];
    const float* Wfb  = (const float*)d_in[9];
    const float* dtb  = (const float*)d_in[10];
    const float* Alog = (const float*)d_in[11];
    const float* Wga  = (const float*)d_in[12];
    const float* Wgb  = (const float*)d_in[13];
    const float* onw  = (const float*)d_in[14];
    const float* Wo   = (const float*)d_in[15];
    float* out = (float*)d_out;

    float *hsr, *qkvp, *q, *k, *v, *eg, *g2, *o, *fab, *beta;
    float *wqkvR, *wfabR, *wfbR, *wgbR, *woR;
    cudaGetSymbolAddress((void**)&hsr, g_hsr);
    cudaGetSymbolAddress((void**)&qkvp, g_qkvp);
    cudaGetSymbolAddress((void**)&q,  g_q);
    cudaGetSymbolAddress((void**)&k,  g_k);
    cudaGetSymbolAddress((void**)&v,  g_v);
    cudaGetSymbolAddress((void**)&eg, g_eg);
    cudaGetSymbolAddress((void**)&g2, g_g2);
    cudaGetSymbolAddress((void**)&o,  g_o);
    cudaGetSymbolAddress((void**)&fab, g_fab);
    cudaGetSymbolAddress((void**)&beta, g_beta);
    cudaGetSymbolAddress((void**)&wqkvR, g_wqkvR);
    cudaGetSymbolAddress((void**)&wfabR, g_wfabR);
    cudaGetSymbolAddress((void**)&wfbR, g_wfbR);
    cudaGetSymbolAddress((void**)&wgbR, g_wgbR);
    cudaGetSymbolAddress((void**)&woR, g_woR);

    cudaFuncSetAttribute(mma_gemm, cudaFuncAttributeMaxDynamicSharedMemorySize, GEMM_SMEM);

    const dim3 blk(256);

    // 1-3: preps
    prep_w4<<<(TT * HID / 4 + 255) / 256, blk>>>((const float4*)hs, (float4*)hsr, TT * HID / 4);
    prep_wqkv<<<(HID * NQKV / 4 + 255) / 256, blk>>>((const float4*)Wq, (const float4*)Wk,
                                                     (const float4*)Wv, (float4*)wqkvR,
                                                     HID * NQKV / 4);
    prep_wfab<<<(HID * NFAB / 4 + 255) / 256, blk>>>((const float4*)Wfa, (const float4*)Wga,
                                                     (const float4*)Wb, (float4*)wfabR,
                                                     HID * NFAB / 4);

    // 4-6: GEMMs (profiling window) — fused qkv in two halves + fused fa/ga/beta
    mma_gemm<<<dim3(48, 32), blk, GEMM_SMEM>>>(hsr, HID, wqkvR, NQKV, qkvp, NQKV,
                                               NQKV / 2, HID, 0);
    mma_gemm<<<dim3(48, 32), blk, GEMM_SMEM>>>(hsr, HID, wqkvR + NQKV / 2, NQKV,
                                               qkvp + NQKV / 2, NQKV, NQKV / 2, HID, 0);
    mma_gemm<<<dim3(3, 32), blk, GEMM_SMEM>>>(hsr, HID, wfabR, NFAB, fab, NFAB,
                                              288, HID, 256);

    // convs + beta
    conv_silu_k<<<TP / 256, blk>>>(qkvp,          cq, q, 0.08838834764831845f);
    conv_silu_k<<<TP / 256, blk>>>(qkvp + PP,     ck, k, 1.f);
    conv_silu_k<<<TP / 256, blk>>>(qkvp + 2 * PP, cv, v, 1.f);
    beta_k<<<(TT * NH + 255) / 256, blk>>>(fab, beta);

    // gate GEMMs (A = fa / ga slices of fab)
    prep_w4<<<(HD * PP / 4 + 255) / 256, blk>>>((const float4*)Wfb, (float4*)wfbR, HD * PP / 4);
    mma_gemm<<<dim3(32, 32), blk, GEMM_SMEM>>>(fab, NFAB, wfbR, PP, eg, PP, PP, HD, 0);
    gate_k<<<TP / 256, blk>>>(eg, dtb, Alog);
    prep_w4<<<(HD * PP / 4 + 255) / 256, blk>>>((const float4*)Wgb, (float4*)wgbR, HD * PP / 4);
    mma_gemm<<<dim3(32, 32), blk, GEMM_SMEM>>>(fab + 128, NFAB, wgbR, PP, g2, PP, PP, HD, 0);

    // sequential KDA scan
    scan_k<<<dim3(4, NH), blk>>>(q, k, v, eg, beta, o);

    // gated rmsnorm + output projection
    rmsnorm_k<<<(TT * NH * 32) / 256, blk>>>(o, g2, onw);
    prep_w4<<<(PP * HID / 4 + 255) / 256, blk>>>((const float4*)Wo, (float4*)woR, PP * HID / 4);
    mma_gemm<<<dim3(16, 32), blk, GEMM_SMEM>>>(o, PP, woR, HID, out, HID, HID, PP, 0);
}